// round 1
// baseline (speedup 1.0000x reference)
#include <cuda_runtime.h>
#include <math.h>

#define BATCH 8
#define CCH 96
#define HH 96
#define WW 96
#define HW (HH*WW)                 // 9216
#define NPIX 7077888               // 8*96*96*96
#define N1OUT 14155776             // 8*192*96*96

// ---------------- scratch (static __device__, no allocation) ----------------
__device__ float g_y1[NPIX];
__device__ float g_y2[NPIX];
__device__ float g_q [NPIX];
__device__ float g_k [NPIX];
__device__ float g_v [NPIX];
__device__ float g_y3[NPIX];
__device__ float g_attn[BATCH*CCH*CCH*9];   // [b][ck][cq][p]
__device__ float g_mean[3*CCH];
__device__ float g_istd[3*CCH];

// ---------------- generic 3x3 same-padding conv ----------------
// input channels [0,csplit) come from inA, [csplit,cin) from inB  (virtual concat)
// weight layout OIHW: wgt[((co*cin)+ci)*9 + kh*3+kw], optional per-batch stride.
// Block: 16x16 threads -> 32x32 output tile, 4 output channels, 2x2 px/thread.
__global__ __launch_bounds__(256, 2)
void conv3x3_kernel(const float* __restrict__ inA, const float* __restrict__ inB,
                    int csplit, int cin,
                    const float* __restrict__ wgt, long wbstride,
                    float* __restrict__ out)
{
    const int tx = threadIdx.x, ty = threadIdx.y;
    const int tid = ty*16 + tx;
    const int tile = blockIdx.x;                    // 0..8  (3x3 tiles of 32)
    const int h0 = (tile/3)*32, w0 = (tile%3)*32;
    const int co0 = blockIdx.y*4;
    const int b = blockIdx.z;

    __shared__ __align__(16) float wshp[4*192*12];      // padded 9->12 for float4
    __shared__ __align__(16) float patch[2][34*36];     // double-buffered input tile

    // stage weights for this (b, co-group) into smem (contiguous copy)
    const float* wb = wgt + (size_t)wbstride * b + (size_t)co0 * cin * 9;
    for (int e = tid; e < 4*cin*9; e += 256) {
        int kqci = e/9, t = e - kqci*9;
        wshp[kqci*12 + t] = wb[e];
    }

    // prologue: load ci=0 patch into buf 0
    {
        const float* src = inA + (size_t)b*csplit*HW;
        for (int e = tid; e < 34*34; e += 256) {
            int r = e/34, c = e - r*34;
            int gh = h0 + r - 1, gw = w0 + c - 1;
            patch[0][r*36 + c] =
                (gh>=0 && gh<HH && gw>=0 && gw<WW) ? src[gh*WW+gw] : 0.f;
        }
    }
    __syncthreads();

    float acc[4][2][2];
    #pragma unroll
    for (int kq=0;kq<4;kq++)
        #pragma unroll
        for (int dy=0;dy<2;dy++)
            #pragma unroll
            for (int dx=0;dx<2;dx++) acc[kq][dy][dx]=0.f;

    for (int ci = 0; ci < cin; ci++) {
        const int buf = ci & 1;

        // prefetch ci+1 into the other buffer (overlaps with FMAs below)
        const int nci = ci + 1;
        if (nci < cin) {
            const float* src = (nci < csplit)
                ? inA + ((size_t)b*csplit + nci)*HW
                : inB + ((size_t)b*(cin-csplit) + (nci-csplit))*HW;
            float vals[5];
            #pragma unroll
            for (int it = 0; it < 5; it++) {
                int e = tid + it*256;
                float vv = 0.f;
                if (e < 34*34) {
                    int r = e/34, c = e - r*34;
                    int gh = h0 + r - 1, gw = w0 + c - 1;
                    if (gh>=0 && gh<HH && gw>=0 && gw<WW) vv = src[gh*WW+gw];
                }
                vals[it] = vv;
            }
            #pragma unroll
            for (int it = 0; it < 5; it++) {
                int e = tid + it*256;
                if (e < 34*34) {
                    int r = e/34, c = e - r*34;
                    patch[buf^1][r*36 + c] = vals[it];
                }
            }
        }

        // weights -> registers (aligned float4 from padded smem)
        float wreg[4][9];
        #pragma unroll
        for (int kq=0;kq<4;kq++) {
            const float4* wp = (const float4*)&wshp[(kq*cin+ci)*12];
            float4 a = wp[0], bq = wp[1];
            wreg[kq][0]=a.x;  wreg[kq][1]=a.y;  wreg[kq][2]=a.z;  wreg[kq][3]=a.w;
            wreg[kq][4]=bq.x; wreg[kq][5]=bq.y; wreg[kq][6]=bq.z; wreg[kq][7]=bq.w;
            wreg[kq][8]=wshp[(kq*cin+ci)*12 + 8];
        }

        // 4x4 pixel neighborhood -> registers (float2 loads, 8B aligned)
        float pv[4][4];
        #pragma unroll
        for (int r=0;r<4;r++) {
            const float2* pp = (const float2*)&patch[buf][(2*ty+r)*36 + 2*tx];
            float2 u = pp[0], v2 = pp[1];
            pv[r][0]=u.x; pv[r][1]=u.y; pv[r][2]=v2.x; pv[r][3]=v2.y;
        }

        // 144 FMAs
        #pragma unroll
        for (int kq=0;kq<4;kq++)
            #pragma unroll
            for (int dy=0;dy<2;dy++)
                #pragma unroll
                for (int dx=0;dx<2;dx++) {
                    float s = acc[kq][dy][dx];
                    #pragma unroll
                    for (int i=0;i<3;i++)
                        #pragma unroll
                        for (int j=0;j<3;j++)
                            s = fmaf(pv[dy+i][dx+j], wreg[kq][i*3+j], s);
                    acc[kq][dy][dx] = s;
                }
        __syncthreads();   // one barrier per ci (double buffer)
    }

    #pragma unroll
    for (int kq=0;kq<4;kq++)
        #pragma unroll
        for (int dy=0;dy<2;dy++)
            #pragma unroll
            for (int dx=0;dx<2;dx++) {
                int h = h0 + 2*ty + dy, w = w0 + 2*tx + dx;
                out[(((size_t)b*CCH + co0+kq)*HH + h)*WW + w] = acc[kq][dy][dx];
            }
}

// ---------------- attention GEMM ----------------
// attn_raw[b,p,cq,ck] = sum over 32x32 lattice (h=3hh+i, w=3ww+j) of q*k
// written transposed into g_attn[((b*96+ck)*96+cq)*9 + p]
__global__ __launch_bounds__(256)
void attn_gemm_kernel(const float* __restrict__ q, const float* __restrict__ k,
                      float* __restrict__ attn)
{
    const int p = blockIdx.x;        // 0..8
    const int b = blockIdx.y;        // 0..7
    const int i = p/3, j = p - 3*(p/3);
    const int tid = threadIdx.y*16 + threadIdx.x;

    __shared__ float Qs[16][96];
    __shared__ float Ks[16][96];

    float acc[6][6];
    #pragma unroll
    for (int r=0;r<6;r++)
        #pragma unroll
        for (int s=0;s<6;s++) acc[r][s]=0.f;

    for (int l0 = 0; l0 < 1024; l0 += 16) {
        #pragma unroll
        for (int it = 0; it < 6; it++) {
            int e = tid + it*256;                 // 16*96 = 1536 = 6*256
            int kk = e/96, c = e - kk*96;
            int l = l0 + kk;
            int gh = 3*(l>>5) + i, gw = 3*(l&31) + j;
            size_t off = ((size_t)(b*CCH + c)*HH + gh)*WW + gw;
            Qs[kk][c] = q[off];
            Ks[kk][c] = k[off];
        }
        __syncthreads();
        #pragma unroll
        for (int kk=0; kk<16; kk++) {
            float rq[6], rk[6];
            #pragma unroll
            for (int r=0;r<6;r++) {
                rq[r] = Qs[kk][threadIdx.y*6 + r];
                rk[r] = Ks[kk][threadIdx.x*6 + r];
            }
            #pragma unroll
            for (int r=0;r<6;r++)
                #pragma unroll
                for (int s=0;s<6;s++)
                    acc[r][s] = fmaf(rq[r], rk[s], acc[r][s]);
        }
        __syncthreads();
    }
    #pragma unroll
    for (int r=0;r<6;r++)
        #pragma unroll
        for (int s=0;s<6;s++) {
            int cq = threadIdx.y*6 + r, ck = threadIdx.x*6 + s;
            attn[((size_t)(b*CCH + ck)*CCH + cq)*9 + p] = acc[r][s];
        }
}

// ---------------- softmax over 864 per (b, ck) row (scale folded in) --------
__global__ __launch_bounds__(256)
void softmax_kernel(float* __restrict__ attn)
{
    float* row = attn + (size_t)blockIdx.x * 864;
    const float scale = 0.034020690871988585f;   // 1/sqrt(864)
    const int tid = threadIdx.x;
    __shared__ float red[256];

    float v[4];
    float mx = -1e30f;
    #pragma unroll
    for (int it=0; it<4; it++) {
        int idx = tid + it*256;
        v[it] = (idx < 864) ? row[idx]*scale : -1e30f;
        mx = fmaxf(mx, v[it]);
    }
    red[tid] = mx; __syncthreads();
    for (int s=128; s>0; s>>=1) { if (tid<s) red[tid]=fmaxf(red[tid],red[tid+s]); __syncthreads(); }
    mx = red[0]; __syncthreads();

    float sum = 0.f;
    #pragma unroll
    for (int it=0; it<4; it++) {
        int idx = tid + it*256;
        v[it] = (idx < 864) ? expf(v[it]-mx) : 0.f;
        sum += v[it];
    }
    red[tid] = sum; __syncthreads();
    for (int s=128; s>0; s>>=1) { if (tid<s) red[tid]+=red[tid+s]; __syncthreads(); }
    float inv = 1.f/red[0];

    #pragma unroll
    for (int it=0; it<4; it++) {
        int idx = tid + it*256;
        if (idx < 864) row[idx] = v[it]*inv;
    }
}

// ---------------- batchnorm statistics (biased var, training mode) ----------
__global__ __launch_bounds__(256)
void bnstats_kernel(const float* __restrict__ y1, const float* __restrict__ y2,
                    const float* __restrict__ y3,
                    float* __restrict__ meanv, float* __restrict__ istdv)
{
    const int t = blockIdx.x / CCH, c = blockIdx.x - t*CCH;
    const float* src = (t==0) ? y1 : (t==1) ? y2 : y3;
    float s = 0.f, sq = 0.f;
    for (int e = threadIdx.x; e < BATCH*HW; e += 256) {
        int b = e / HW, hw = e - b*HW;
        float vv = src[((size_t)b*CCH + c)*HW + hw];
        s += vv; sq = fmaf(vv, vv, sq);
    }
    __shared__ float sh1[256], sh2[256];
    sh1[threadIdx.x]=s; sh2[threadIdx.x]=sq;
    __syncthreads();
    for (int st=128; st>0; st>>=1) {
        if (threadIdx.x < st) { sh1[threadIdx.x]+=sh1[threadIdx.x+st]; sh2[threadIdx.x]+=sh2[threadIdx.x+st]; }
        __syncthreads();
    }
    if (threadIdx.x==0) {
        const float invN = 1.f / (float)(BATCH*HW);
        float m = sh1[0]*invN;
        float var = sh2[0]*invN - m*m;
        meanv[blockIdx.x] = m;
        istdv[blockIdx.x] = rsqrtf(var + 1e-5f);
    }
}

// ---------------- final fuse: out = (x+y, x) ----------------
__global__ __launch_bounds__(256)
void finalize_kernel(const float* __restrict__ x1, const float* __restrict__ x2,
                     const float* __restrict__ y1, const float* __restrict__ y2,
                     const float* __restrict__ y3,
                     const float* __restrict__ meanv, const float* __restrict__ istdv,
                     float* __restrict__ out, int writeSecond)
{
    int idx = blockIdx.x*256 + threadIdx.x;
    if (idx >= N1OUT) return;
    int hw = idx % HW;
    int c  = (idx / HW) % (2*CCH);
    int b  = idx / (HW*2*CCH);
    float xv, yv;
    if (c < CCH) {
        size_t off = ((size_t)b*CCH + c)*HW + hw;
        xv = x1[off];
        float a = (y1[off]-meanv[c])       * istdv[c];
        float g = (y2[off]-meanv[CCH+c])   * istdv[CCH+c];
        yv = a*g;
    } else {
        int cc = c - CCH;
        size_t off = ((size_t)b*CCH + cc)*HW + hw;
        xv = x2[off];
        yv = (y3[off]-meanv[2*CCH+cc]) * istdv[2*CCH+cc];
    }
    out[idx] = xv + yv;
    if (writeSecond) out[N1OUT + idx] = xv;
}

// ---------------- launch ----------------
extern "C" void kernel_launch(void* const* d_in, const int* in_sizes, int n_in,
                              void* d_out, int out_size)
{
    const float* x1  = (const float*)d_in[0];
    const float* x2  = (const float*)d_in[1];
    const float* w1  = (const float*)d_in[2];
    const float* w2  = (const float*)d_in[3];
    const float* wa1 = (const float*)d_in[4];
    const float* wa2 = (const float*)d_in[5];
    const float* wa3 = (const float*)d_in[6];
    float* out = (float*)d_out;

    float *y1,*y2,*q,*k,*v,*y3,*attn,*meanv,*istdv;
    cudaGetSymbolAddress((void**)&y1,   g_y1);
    cudaGetSymbolAddress((void**)&y2,   g_y2);
    cudaGetSymbolAddress((void**)&q,    g_q);
    cudaGetSymbolAddress((void**)&k,    g_k);
    cudaGetSymbolAddress((void**)&v,    g_v);
    cudaGetSymbolAddress((void**)&y3,   g_y3);
    cudaGetSymbolAddress((void**)&attn, g_attn);
    cudaGetSymbolAddress((void**)&meanv,g_mean);
    cudaGetSymbolAddress((void**)&istdv,g_istd);

    dim3 cblk(16,16);
    dim3 cgrid(9, 24, 8);   // 3x3 tiles of 32, 24 co-groups of 4, 8 batches

    // fixed-weight convs
    conv3x3_kernel<<<cgrid, cblk>>>(x1, x1, 96,  96, w1,  0, y1);
    conv3x3_kernel<<<cgrid, cblk>>>(x2, x2, 96,  96, w2,  0, y2);
    conv3x3_kernel<<<cgrid, cblk>>>(x1, x2, 96, 192, wa1, 0, q);
    conv3x3_kernel<<<cgrid, cblk>>>(x1, x2, 96, 192, wa2, 0, k);
    conv3x3_kernel<<<cgrid, cblk>>>(x1, x2, 96, 192, wa3, 0, v);

    // attention weights
    attn_gemm_kernel<<<dim3(9,8), cblk>>>(q, k, attn);
    softmax_kernel<<<BATCH*CCH, 256>>>(attn);

    // attn @ v_unf  ==  per-batch 3x3 conv of v with weight A[b]
    conv3x3_kernel<<<cgrid, cblk>>>(v, v, 96, 96, attn, (long)CCH*CCH*9, y3);

    // batchnorm stats + fused epilogue
    bnstats_kernel<<<3*CCH, 256>>>(y1, y2, y3, meanv, istdv);
    int writeSecond = (out_size >= 2*N1OUT) ? 1 : 0;
    finalize_kernel<<<(N1OUT + 255)/256, 256>>>(x1, x2, y1, y2, y3, meanv, istdv, out, writeSecond);
}

// round 2
// speedup vs baseline: 1.2788x; 1.2788x over previous
#include <cuda_runtime.h>
#include <math.h>

#define BATCH 8
#define CCH 96
#define HH 96
#define WW 96
#define HW (HH*WW)                 // 9216
#define NPIX 7077888               // 8*96*96*96
#define N1OUT 14155776             // 8*192*96*96
#define CHUNK 16

// ---------------- scratch (static __device__, no allocation) ----------------
__device__ float g_y1[NPIX];
__device__ float g_y2[NPIX];
__device__ float g_q [NPIX];
__device__ float g_k [NPIX];
__device__ float g_v [NPIX];
__device__ float g_y3[NPIX];
__device__ float g_attn[BATCH*CCH*CCH*9];   // [b][ck][cq][p]
__device__ float g_mean[3*CCH];
__device__ float g_istd[3*CCH];

// ---------------- generic 3x3 same-padding conv ----------------
// input channels [0,csplit) from inA, [csplit,cin) from inB  (virtual concat)
// weight layout OIHW: wgt[((co*cin)+ci)*9 + tap], optional per-batch stride.
// Block: 16x16 threads -> 32x32 output tile, 8 output channels, 2x2 px/thread.
__global__ __launch_bounds__(256, 2)
void conv3x3_kernel(const float* __restrict__ inA, const float* __restrict__ inB,
                    int csplit, int cin,
                    const float* __restrict__ wgt, long wbstride,
                    float* __restrict__ out)
{
    const int tx = threadIdx.x, ty = threadIdx.y;
    const int tid = ty*16 + tx;
    const int tile = blockIdx.x;                    // 0..8 (3x3 tiles of 32)
    const int h0 = (tile/3)*32, w0 = (tile%3)*32;
    const int co0 = blockIdx.y*8;
    const int b = blockIdx.z;

    __shared__ __align__(16) float patch[2][34*36];          // 9792 B
    __shared__ __align__(16) float wsm[2][CHUNK][8][12];     // 12288 B

    const float* wb = wgt + (size_t)wbstride * b + (size_t)co0 * cin * 9;

    // ---- hoisted patch-prefetch geometry (constant across ci) ----
    int  goff[5], soff[5];
    bool lpred[5], spred[5];
    #pragma unroll
    for (int it = 0; it < 5; it++) {
        int e = tid + it*256;
        int r = e/34, c = e - r*34;
        int gh = h0 + r - 1, gw = w0 + c - 1;
        bool inpatch = (e < 34*34);
        bool ok = inpatch && (gh>=0) && (gh<HH) && (gw>=0) && (gw<WW);
        lpred[it] = ok;
        spred[it] = inpatch;
        goff[it]  = ok ? gh*WW + gw : 0;
        soff[it]  = inpatch ? r*36 + c : 0;
    }

    // ---- hoisted weight-staging geometry: tid<72 owns one (co,tap) ----
    const bool wstage = (tid < 72);
    const int  wco = tid/9, wtap = tid - 9*(tid/9);
    const float* wsrc = wb + (size_t)wco*cin*9 + wtap;   // + ci*9 per staged ci

    // ---- prologue: stage weight chunk 0, patch for ci=0 ----
    #pragma unroll
    for (int it = 0; it < 5; it++) {
        int e = tid + it*256;
        if (e < CHUNK*72) {
            int cil = e/72, rm = e - cil*72;
            int co = rm/9, tap = rm - co*9;
            wsm[0][cil][co][tap] = wb[((size_t)co*cin + cil)*9 + tap];
        }
    }
    {
        const float* src = inA + (size_t)b*csplit*HW;
        #pragma unroll
        for (int it = 0; it < 5; it++)
            if (spred[it])
                patch[0][soff[it]] = lpred[it] ? __ldg(src + goff[it]) : 0.f;
    }
    __syncthreads();

    float acc[8][4];
    #pragma unroll
    for (int co=0;co<8;co++)
        #pragma unroll
        for (int p=0;p<4;p++) acc[co][p]=0.f;

    for (int ci = 0; ci < cin; ci++) {
        const int buf  = ci & 1;
        const int cil  = ci & (CHUNK-1);
        const int bufw = (ci >> 4) & 1;

        // prefetch next input channel's patch into the other buffer
        const int nci = ci + 1;
        if (nci < cin) {
            const float* src = (nci < csplit)
                ? inA + ((size_t)b*csplit + nci)*HW
                : inB + ((size_t)b*(cin-csplit) + (nci-csplit))*HW;
            float vals[5];
            #pragma unroll
            for (int it = 0; it < 5; it++)
                vals[it] = lpred[it] ? __ldg(src + goff[it]) : 0.f;
            #pragma unroll
            for (int it = 0; it < 5; it++)
                if (spred[it]) patch[buf^1][soff[it]] = vals[it];
        }

        // stage one weight of the NEXT chunk (source ci = chunkbase+16+cil)
        {
            int nc = (ci | (CHUNK-1)) + 1 + cil;
            if (wstage && nc < cin)
                wsm[bufw^1][cil][wco][wtap] = __ldg(wsrc + (size_t)nc*9);
        }

        // 4x4 pixel neighborhood -> registers
        float pv[4][4];
        #pragma unroll
        for (int r=0;r<4;r++) {
            const float2* pp = (const float2*)&patch[buf][(2*ty+r)*36 + 2*tx];
            float2 u = pp[0], v2 = pp[1];
            pv[r][0]=u.x; pv[r][1]=u.y; pv[r][2]=v2.x; pv[r][3]=v2.y;
        }

        // 8 output channels x 4 px x 9 taps = 288 FMA
        #pragma unroll
        for (int co=0;co<8;co++) {
            const float4* wp = (const float4*)&wsm[bufw][cil][co][0];
            float4 a = wp[0], b4 = wp[1];
            float w8 = wsm[bufw][cil][co][8];
            float w[9] = {a.x,a.y,a.z,a.w,b4.x,b4.y,b4.z,b4.w,w8};
            #pragma unroll
            for (int dy=0;dy<2;dy++)
                #pragma unroll
                for (int dx=0;dx<2;dx++) {
                    float s = acc[co][dy*2+dx];
                    #pragma unroll
                    for (int i=0;i<3;i++)
                        #pragma unroll
                        for (int j=0;j<3;j++)
                            s = fmaf(pv[dy+i][dx+j], w[i*3+j], s);
                    acc[co][dy*2+dx] = s;
                }
        }
        __syncthreads();
    }

    #pragma unroll
    for (int co=0;co<8;co++)
        #pragma unroll
        for (int dy=0;dy<2;dy++)
            #pragma unroll
            for (int dx=0;dx<2;dx++) {
                int h = h0 + 2*ty + dy, w = w0 + 2*tx + dx;
                out[(((size_t)b*CCH + co0+co)*HH + h)*WW + w] = acc[co][dy*2+dx];
            }
}

// ---------------- attention GEMM ----------------
__global__ __launch_bounds__(256)
void attn_gemm_kernel(const float* __restrict__ q, const float* __restrict__ k,
                      float* __restrict__ attn)
{
    const int p = blockIdx.x;        // 0..8
    const int b = blockIdx.y;        // 0..7
    const int i = p/3, j = p - 3*(p/3);
    const int tid = threadIdx.y*16 + threadIdx.x;

    __shared__ float Qs[16][96];
    __shared__ float Ks[16][96];

    float acc[6][6];
    #pragma unroll
    for (int r=0;r<6;r++)
        #pragma unroll
        for (int s=0;s<6;s++) acc[r][s]=0.f;

    for (int l0 = 0; l0 < 1024; l0 += 16) {
        #pragma unroll
        for (int it = 0; it < 6; it++) {
            int e = tid + it*256;                 // 16*96 = 1536 = 6*256
            int kk = e/96, c = e - kk*96;
            int l = l0 + kk;
            int gh = 3*(l>>5) + i, gw = 3*(l&31) + j;
            size_t off = ((size_t)(b*CCH + c)*HH + gh)*WW + gw;
            Qs[kk][c] = q[off];
            Ks[kk][c] = k[off];
        }
        __syncthreads();
        #pragma unroll
        for (int kk=0; kk<16; kk++) {
            float rq[6], rk[6];
            #pragma unroll
            for (int r=0;r<6;r++) {
                rq[r] = Qs[kk][threadIdx.y*6 + r];
                rk[r] = Ks[kk][threadIdx.x*6 + r];
            }
            #pragma unroll
            for (int r=0;r<6;r++)
                #pragma unroll
                for (int s=0;s<6;s++)
                    acc[r][s] = fmaf(rq[r], rk[s], acc[r][s]);
        }
        __syncthreads();
    }
    #pragma unroll
    for (int r=0;r<6;r++)
        #pragma unroll
        for (int s=0;s<6;s++) {
            int cq = threadIdx.y*6 + r, ck = threadIdx.x*6 + s;
            attn[((size_t)(b*CCH + ck)*CCH + cq)*9 + p] = acc[r][s];
        }
}

// ---------------- softmax over 864 per (b, ck) row ----------------
__global__ __launch_bounds__(256)
void softmax_kernel(float* __restrict__ attn)
{
    float* row = attn + (size_t)blockIdx.x * 864;
    const float scale = 0.034020690871988585f;   // 1/sqrt(864)
    const int tid = threadIdx.x;
    __shared__ float red[256];

    float v[4];
    float mx = -1e30f;
    #pragma unroll
    for (int it=0; it<4; it++) {
        int idx = tid + it*256;
        v[it] = (idx < 864) ? row[idx]*scale : -1e30f;
        mx = fmaxf(mx, v[it]);
    }
    red[tid] = mx; __syncthreads();
    for (int s=128; s>0; s>>=1) { if (tid<s) red[tid]=fmaxf(red[tid],red[tid+s]); __syncthreads(); }
    mx = red[0]; __syncthreads();

    float sum = 0.f;
    #pragma unroll
    for (int it=0; it<4; it++) {
        int idx = tid + it*256;
        v[it] = (idx < 864) ? expf(v[it]-mx) : 0.f;
        sum += v[it];
    }
    red[tid] = sum; __syncthreads();
    for (int s=128; s>0; s>>=1) { if (tid<s) red[tid]+=red[tid+s]; __syncthreads(); }
    float inv = 1.f/red[0];

    #pragma unroll
    for (int it=0; it<4; it++) {
        int idx = tid + it*256;
        if (idx < 864) row[idx] = v[it]*inv;
    }
}

// ---------------- batchnorm statistics (biased var) ----------------
__global__ __launch_bounds__(256)
void bnstats_kernel(const float* __restrict__ y1, const float* __restrict__ y2,
                    const float* __restrict__ y3,
                    float* __restrict__ meanv, float* __restrict__ istdv)
{
    const int t = blockIdx.x / CCH, c = blockIdx.x - t*CCH;
    const float* src = (t==0) ? y1 : (t==1) ? y2 : y3;
    float s = 0.f, sq = 0.f;
    for (int e = threadIdx.x; e < BATCH*HW; e += 256) {
        int b = e / HW, hw = e - b*HW;
        float vv = src[((size_t)b*CCH + c)*HW + hw];
        s += vv; sq = fmaf(vv, vv, sq);
    }
    __shared__ float sh1[256], sh2[256];
    sh1[threadIdx.x]=s; sh2[threadIdx.x]=sq;
    __syncthreads();
    for (int st=128; st>0; st>>=1) {
        if (threadIdx.x < st) { sh1[threadIdx.x]+=sh1[threadIdx.x+st]; sh2[threadIdx.x]+=sh2[threadIdx.x+st]; }
        __syncthreads();
    }
    if (threadIdx.x==0) {
        const float invN = 1.f / (float)(BATCH*HW);
        float m = sh1[0]*invN;
        float var = sh2[0]*invN - m*m;
        meanv[blockIdx.x] = m;
        istdv[blockIdx.x] = rsqrtf(var + 1e-5f);
    }
}

// ---------------- final fuse: out = (x+y, x) ----------------
__global__ __launch_bounds__(256)
void finalize_kernel(const float* __restrict__ x1, const float* __restrict__ x2,
                     const float* __restrict__ y1, const float* __restrict__ y2,
                     const float* __restrict__ y3,
                     const float* __restrict__ meanv, const float* __restrict__ istdv,
                     float* __restrict__ out, int writeSecond)
{
    int idx = blockIdx.x*256 + threadIdx.x;
    if (idx >= N1OUT) return;
    int hw = idx % HW;
    int c  = (idx / HW) % (2*CCH);
    int b  = idx / (HW*2*CCH);
    float xv, yv;
    if (c < CCH) {
        size_t off = ((size_t)b*CCH + c)*HW + hw;
        xv = x1[off];
        float a = (y1[off]-meanv[c])       * istdv[c];
        float g = (y2[off]-meanv[CCH+c])   * istdv[CCH+c];
        yv = a*g;
    } else {
        int cc = c - CCH;
        size_t off = ((size_t)b*CCH + cc)*HW + hw;
        xv = x2[off];
        yv = (y3[off]-meanv[2*CCH+cc]) * istdv[2*CCH+cc];
    }
    out[idx] = xv + yv;
    if (writeSecond) out[N1OUT + idx] = xv;
}

// ---------------- launch ----------------
extern "C" void kernel_launch(void* const* d_in, const int* in_sizes, int n_in,
                              void* d_out, int out_size)
{
    const float* x1  = (const float*)d_in[0];
    const float* x2  = (const float*)d_in[1];
    const float* w1  = (const float*)d_in[2];
    const float* w2  = (const float*)d_in[3];
    const float* wa1 = (const float*)d_in[4];
    const float* wa2 = (const float*)d_in[5];
    const float* wa3 = (const float*)d_in[6];
    float* out = (float*)d_out;

    float *y1,*y2,*q,*k,*v,*y3,*attn,*meanv,*istdv;
    cudaGetSymbolAddress((void**)&y1,   g_y1);
    cudaGetSymbolAddress((void**)&y2,   g_y2);
    cudaGetSymbolAddress((void**)&q,    g_q);
    cudaGetSymbolAddress((void**)&k,    g_k);
    cudaGetSymbolAddress((void**)&v,    g_v);
    cudaGetSymbolAddress((void**)&y3,   g_y3);
    cudaGetSymbolAddress((void**)&attn, g_attn);
    cudaGetSymbolAddress((void**)&meanv,g_mean);
    cudaGetSymbolAddress((void**)&istdv,g_istd);

    dim3 cblk(16,16);
    dim3 cgrid(9, 12, 8);   // 3x3 tiles of 32, 12 co-groups of 8, 8 batches

    // fixed-weight convs
    conv3x3_kernel<<<cgrid, cblk>>>(x1, x1, 96,  96, w1,  0, y1);
    conv3x3_kernel<<<cgrid, cblk>>>(x2, x2, 96,  96, w2,  0, y2);
    conv3x3_kernel<<<cgrid, cblk>>>(x1, x2, 96, 192, wa1, 0, q);
    conv3x3_kernel<<<cgrid, cblk>>>(x1, x2, 96, 192, wa2, 0, k);
    conv3x3_kernel<<<cgrid, cblk>>>(x1, x2, 96, 192, wa3, 0, v);

    // attention weights
    attn_gemm_kernel<<<dim3(9,8), cblk>>>(q, k, attn);
    softmax_kernel<<<BATCH*CCH, 256>>>(attn);

    // attn @ v_unf  ==  per-batch 3x3 conv of v with weight A[b]
    conv3x3_kernel<<<cgrid, cblk>>>(v, v, 96, 96, attn, (long)CCH*CCH*9, y3);

    // batchnorm stats + fused epilogue
    bnstats_kernel<<<3*CCH, 256>>>(y1, y2, y3, meanv, istdv);
    int writeSecond = (out_size >= 2*N1OUT) ? 1 : 0;
    finalize_kernel<<<(N1OUT + 255)/256, 256>>>(x1, x2, y1, y2, y3, meanv, istdv, out, writeSecond);
}

// round 3
// speedup vs baseline: 1.4365x; 1.1233x over previous
#include <cuda_runtime.h>
#include <math.h>

#define BATCH 8
#define CCH 96
#define HH 96
#define WW 96
#define HW (HH*WW)                 // 9216
#define NPIX 7077888               // 8*96*96*96
#define N1OUT 14155776             // 8*192*96*96
#define CHUNK 16

// ---------------- scratch (static __device__, no allocation) ----------------
__device__ float g_y1[NPIX];
__device__ float g_y2[NPIX];
__device__ float g_q [NPIX];
__device__ float g_k [NPIX];
__device__ float g_v [NPIX];
__device__ float g_y3[NPIX];
__device__ float g_attn[BATCH*CCH*CCH*9];   // [b][ck][cq][p]
__device__ float g_mean[3*CCH];
__device__ float g_istd[3*CCH];

// ---------------- generic 3x3 same-padding conv, f32x2 packed math ----------
// input channels [0,csplit) from inA, [csplit,cin) from inB  (virtual concat)
// weight layout OIHW: wgt[((co*cin)+ci)*9 + tap], optional per-batch stride.
// Block: 16x16 threads -> 32x32 output tile, 8 output channels, 2x2 px/thread.
// Accumulators are fma.rn.f32x2 pairs packed over adjacent output channels.
__global__ __launch_bounds__(256, 2)
void conv3x3_kernel(const float* __restrict__ inA, const float* __restrict__ inB,
                    int csplit, int cin,
                    const float* __restrict__ wgt, long wbstride,
                    float* __restrict__ out)
{
    const int tx = threadIdx.x, ty = threadIdx.y;
    const int tid = ty*16 + tx;
    const int tile = blockIdx.x;                    // 0..8 (3x3 tiles of 32)
    const int h0 = (tile/3)*32, w0 = (tile%3)*32;
    const int co0 = blockIdx.y*8;
    const int b = blockIdx.z;

    __shared__ __align__(16) float patch[2][34*36];           // 9792 B
    __shared__ __align__(16) float wsm[2][CHUNK][9][8];       // co-interleaved, 9216 B

    const float* wb = wgt + (size_t)wbstride * b + (size_t)co0 * cin * 9;

    // ---- hoisted patch-prefetch geometry (constant across ci) ----
    int  goff[5], soff[5];
    bool lpred[5], spred[5];
    #pragma unroll
    for (int it = 0; it < 5; it++) {
        int e = tid + it*256;
        int r = e/34, c = e - r*34;
        int gh = h0 + r - 1, gw = w0 + c - 1;
        bool inpatch = (e < 34*34);
        bool ok = inpatch && (gh>=0) && (gh<HH) && (gw>=0) && (gw<WW);
        lpred[it] = ok;
        spred[it] = inpatch;
        goff[it]  = ok ? gh*WW + gw : 0;
        soff[it]  = inpatch ? r*36 + c : 0;
    }

    // ---- hoisted weight-staging geometry: tid<72 owns one (co,tap) ----
    const bool wstage = (tid < 72);
    const int  wco = tid/9, wtap = tid - 9*(tid/9);
    const float* wsrc = wb + (size_t)wco*cin*9 + wtap;   // + ci*9 per staged ci

    const unsigned wsm_s = (unsigned)__cvta_generic_to_shared(&wsm[0][0][0][0]);

    // ---- prologue: stage weight chunk 0 (co-interleaved), patch for ci=0 ----
    #pragma unroll
    for (int it = 0; it < 5; it++) {
        int e = tid + it*256;
        if (e < CHUNK*72) {
            int cil = e/72, rm = e - cil*72;
            int co = rm/9, tap = rm - co*9;
            wsm[0][cil][tap][co] = wb[((size_t)co*cin + cil)*9 + tap];
        }
    }
    {
        const float* src = inA + (size_t)b*csplit*HW;
        #pragma unroll
        for (int it = 0; it < 5; it++)
            if (spred[it])
                patch[0][soff[it]] = lpred[it] ? __ldg(src + goff[it]) : 0.f;
    }
    __syncthreads();

    // acc2[cop][px]: packed pair over (co=co0+2cop, co0+2cop+1), px = dy*2+dx
    unsigned long long acc2[4][4];
    #pragma unroll
    for (int cp=0;cp<4;cp++)
        #pragma unroll
        for (int p=0;p<4;p++) acc2[cp][p] = 0ULL;

    for (int ci = 0; ci < cin; ci++) {
        const int buf  = ci & 1;
        const int cil  = ci & (CHUNK-1);
        const int bufw = (ci >> 4) & 1;

        // prefetch next input channel's patch into the other buffer
        const int nci = ci + 1;
        if (nci < cin) {
            const float* src = (nci < csplit)
                ? inA + ((size_t)b*csplit + nci)*HW
                : inB + ((size_t)b*(cin-csplit) + (nci-csplit))*HW;
            float vals[5];
            #pragma unroll
            for (int it = 0; it < 5; it++)
                vals[it] = lpred[it] ? __ldg(src + goff[it]) : 0.f;
            #pragma unroll
            for (int it = 0; it < 5; it++)
                if (spred[it]) patch[buf^1][soff[it]] = vals[it];
        }

        // stage one weight of the NEXT chunk (co-interleaved layout)
        {
            int nc = (ci | (CHUNK-1)) + 1 + cil;
            if (wstage && nc < cin)
                wsm[bufw^1][cil][wtap][wco] = __ldg(wsrc + (size_t)nc*9);
        }

        // 4x4 pixel neighborhood -> splatted f32x2 registers {p,p}
        unsigned long long pp[4][4];
        #pragma unroll
        for (int r=0;r<4;r++) {
            const float2* ppix = (const float2*)&patch[buf][(2*ty+r)*36 + 2*tx];
            float2 u = ppix[0], v2 = ppix[1];
            asm("mov.b64 %0, {%1,%1};" : "=l"(pp[r][0]) : "f"(u.x));
            asm("mov.b64 %0, {%1,%1};" : "=l"(pp[r][1]) : "f"(u.y));
            asm("mov.b64 %0, {%1,%1};" : "=l"(pp[r][2]) : "f"(v2.x));
            asm("mov.b64 %0, {%1,%1};" : "=l"(pp[r][3]) : "f"(v2.y));
        }

        // 9 taps x 4 co-pairs x 4 px = 144 FFMA2 (= 288 MACs)
        const unsigned wrow = wsm_s + (unsigned)((bufw*CHUNK + cil)*288);  // bytes
        #pragma unroll
        for (int t=0; t<9; t++) {
            const int i = t/3, j = t - 3*(t/3);
            unsigned long long w01, w23, w45, w67;
            asm volatile("ld.shared.v2.u64 {%0,%1}, [%2];"
                         : "=l"(w01), "=l"(w23) : "r"(wrow + t*32));
            asm volatile("ld.shared.v2.u64 {%0,%1}, [%2];"
                         : "=l"(w45), "=l"(w67) : "r"(wrow + t*32 + 16));
            #pragma unroll
            for (int dy=0;dy<2;dy++)
                #pragma unroll
                for (int dx=0;dx<2;dx++) {
                    const int p = dy*2+dx;
                    unsigned long long px = pp[dy+i][dx+j];
                    asm("fma.rn.f32x2 %0, %1, %2, %0;" : "+l"(acc2[0][p]) : "l"(w01), "l"(px));
                    asm("fma.rn.f32x2 %0, %1, %2, %0;" : "+l"(acc2[1][p]) : "l"(w23), "l"(px));
                    asm("fma.rn.f32x2 %0, %1, %2, %0;" : "+l"(acc2[2][p]) : "l"(w45), "l"(px));
                    asm("fma.rn.f32x2 %0, %1, %2, %0;" : "+l"(acc2[3][p]) : "l"(w67), "l"(px));
                }
        }
        __syncthreads();
    }

    #pragma unroll
    for (int cp=0;cp<4;cp++)
        #pragma unroll
        for (int dy=0;dy<2;dy++)
            #pragma unroll
            for (int dx=0;dx<2;dx++) {
                float lo, hi;
                asm("mov.b64 {%0,%1}, %2;" : "=f"(lo), "=f"(hi) : "l"(acc2[cp][dy*2+dx]));
                int h = h0 + 2*ty + dy, w = w0 + 2*tx + dx;
                size_t base = (((size_t)b*CCH + co0 + 2*cp)*HH + h)*WW + w;
                out[base]      = lo;
                out[base + HW] = hi;
            }
}

// ---------------- attention GEMM ----------------
__global__ __launch_bounds__(256)
void attn_gemm_kernel(const float* __restrict__ q, const float* __restrict__ k,
                      float* __restrict__ attn)
{
    const int p = blockIdx.x;        // 0..8
    const int b = blockIdx.y;        // 0..7
    const int i = p/3, j = p - 3*(p/3);
    const int tid = threadIdx.y*16 + threadIdx.x;

    __shared__ float Qs[16][96];
    __shared__ float Ks[16][96];

    float acc[6][6];
    #pragma unroll
    for (int r=0;r<6;r++)
        #pragma unroll
        for (int s=0;s<6;s++) acc[r][s]=0.f;

    for (int l0 = 0; l0 < 1024; l0 += 16) {
        #pragma unroll
        for (int it = 0; it < 6; it++) {
            int e = tid + it*256;                 // 16*96 = 1536 = 6*256
            int kk = e/96, c = e - kk*96;
            int l = l0 + kk;
            int gh = 3*(l>>5) + i, gw = 3*(l&31) + j;
            size_t off = ((size_t)(b*CCH + c)*HH + gh)*WW + gw;
            Qs[kk][c] = q[off];
            Ks[kk][c] = k[off];
        }
        __syncthreads();
        #pragma unroll
        for (int kk=0; kk<16; kk++) {
            float rq[6], rk[6];
            #pragma unroll
            for (int r=0;r<6;r++) {
                rq[r] = Qs[kk][threadIdx.y*6 + r];
                rk[r] = Ks[kk][threadIdx.x*6 + r];
            }
            #pragma unroll
            for (int r=0;r<6;r++)
                #pragma unroll
                for (int s=0;s<6;s++)
                    acc[r][s] = fmaf(rq[r], rk[s], acc[r][s]);
        }
        __syncthreads();
    }
    #pragma unroll
    for (int r=0;r<6;r++)
        #pragma unroll
        for (int s=0;s<6;s++) {
            int cq = threadIdx.y*6 + r, ck = threadIdx.x*6 + s;
            attn[((size_t)(b*CCH + ck)*CCH + cq)*9 + p] = acc[r][s];
        }
}

// ---------------- softmax over 864 per (b, ck) row ----------------
__global__ __launch_bounds__(256)
void softmax_kernel(float* __restrict__ attn)
{
    float* row = attn + (size_t)blockIdx.x * 864;
    const float scale = 0.034020690871988585f;   // 1/sqrt(864)
    const int tid = threadIdx.x;
    __shared__ float red[256];

    float v[4];
    float mx = -1e30f;
    #pragma unroll
    for (int it=0; it<4; it++) {
        int idx = tid + it*256;
        v[it] = (idx < 864) ? row[idx]*scale : -1e30f;
        mx = fmaxf(mx, v[it]);
    }
    red[tid] = mx; __syncthreads();
    for (int s=128; s>0; s>>=1) { if (tid<s) red[tid]=fmaxf(red[tid],red[tid+s]); __syncthreads(); }
    mx = red[0]; __syncthreads();

    float sum = 0.f;
    #pragma unroll
    for (int it=0; it<4; it++) {
        int idx = tid + it*256;
        v[it] = (idx < 864) ? expf(v[it]-mx) : 0.f;
        sum += v[it];
    }
    red[tid] = sum; __syncthreads();
    for (int s=128; s>0; s>>=1) { if (tid<s) red[tid]+=red[tid+s]; __syncthreads(); }
    float inv = 1.f/red[0];

    #pragma unroll
    for (int it=0; it<4; it++) {
        int idx = tid + it*256;
        if (idx < 864) row[idx] = v[it]*inv;
    }
}

// ---------------- batchnorm statistics (biased var) ----------------
__global__ __launch_bounds__(256)
void bnstats_kernel(const float* __restrict__ y1, const float* __restrict__ y2,
                    const float* __restrict__ y3,
                    float* __restrict__ meanv, float* __restrict__ istdv)
{
    const int t = blockIdx.x / CCH, c = blockIdx.x - t*CCH;
    const float* src = (t==0) ? y1 : (t==1) ? y2 : y3;
    float s = 0.f, sq = 0.f;
    for (int e = threadIdx.x; e < BATCH*HW; e += 256) {
        int b = e / HW, hw = e - b*HW;
        float vv = src[((size_t)b*CCH + c)*HW + hw];
        s += vv; sq = fmaf(vv, vv, sq);
    }
    __shared__ float sh1[256], sh2[256];
    sh1[threadIdx.x]=s; sh2[threadIdx.x]=sq;
    __syncthreads();
    for (int st=128; st>0; st>>=1) {
        if (threadIdx.x < st) { sh1[threadIdx.x]+=sh1[threadIdx.x+st]; sh2[threadIdx.x]+=sh2[threadIdx.x+st]; }
        __syncthreads();
    }
    if (threadIdx.x==0) {
        const float invN = 1.f / (float)(BATCH*HW);
        float m = sh1[0]*invN;
        float var = sh2[0]*invN - m*m;
        meanv[blockIdx.x] = m;
        istdv[blockIdx.x] = rsqrtf(var + 1e-5f);
    }
}

// ---------------- final fuse: out = (x+y, x) ----------------
__global__ __launch_bounds__(256)
void finalize_kernel(const float* __restrict__ x1, const float* __restrict__ x2,
                     const float* __restrict__ y1, const float* __restrict__ y2,
                     const float* __restrict__ y3,
                     const float* __restrict__ meanv, const float* __restrict__ istdv,
                     float* __restrict__ out, int writeSecond)
{
    int idx = blockIdx.x*256 + threadIdx.x;
    if (idx >= N1OUT) return;
    int hw = idx % HW;
    int c  = (idx / HW) % (2*CCH);
    int b  = idx / (HW*2*CCH);
    float xv, yv;
    if (c < CCH) {
        size_t off = ((size_t)b*CCH + c)*HW + hw;
        xv = x1[off];
        float a = (y1[off]-meanv[c])       * istdv[c];
        float g = (y2[off]-meanv[CCH+c])   * istdv[CCH+c];
        yv = a*g;
    } else {
        int cc = c - CCH;
        size_t off = ((size_t)b*CCH + cc)*HW + hw;
        xv = x2[off];
        yv = (y3[off]-meanv[2*CCH+cc]) * istdv[2*CCH+cc];
    }
    out[idx] = xv + yv;
    if (writeSecond) out[N1OUT + idx] = xv;
}

// ---------------- launch ----------------
extern "C" void kernel_launch(void* const* d_in, const int* in_sizes, int n_in,
                              void* d_out, int out_size)
{
    const float* x1  = (const float*)d_in[0];
    const float* x2  = (const float*)d_in[1];
    const float* w1  = (const float*)d_in[2];
    const float* w2  = (const float*)d_in[3];
    const float* wa1 = (const float*)d_in[4];
    const float* wa2 = (const float*)d_in[5];
    const float* wa3 = (const float*)d_in[6];
    float* out = (float*)d_out;

    float *y1,*y2,*q,*k,*v,*y3,*attn,*meanv,*istdv;
    cudaGetSymbolAddress((void**)&y1,   g_y1);
    cudaGetSymbolAddress((void**)&y2,   g_y2);
    cudaGetSymbolAddress((void**)&q,    g_q);
    cudaGetSymbolAddress((void**)&k,    g_k);
    cudaGetSymbolAddress((void**)&v,    g_v);
    cudaGetSymbolAddress((void**)&y3,   g_y3);
    cudaGetSymbolAddress((void**)&attn, g_attn);
    cudaGetSymbolAddress((void**)&meanv,g_mean);
    cudaGetSymbolAddress((void**)&istdv,g_istd);

    dim3 cblk(16,16);
    dim3 cgrid(9, 12, 8);   // 3x3 tiles of 32, 12 co-groups of 8, 8 batches

    // fixed-weight convs
    conv3x3_kernel<<<cgrid, cblk>>>(x1, x1, 96,  96, w1,  0, y1);
    conv3x3_kernel<<<cgrid, cblk>>>(x2, x2, 96,  96, w2,  0, y2);
    conv3x3_kernel<<<cgrid, cblk>>>(x1, x2, 96, 192, wa1, 0, q);
    conv3x3_kernel<<<cgrid, cblk>>>(x1, x2, 96, 192, wa2, 0, k);
    conv3x3_kernel<<<cgrid, cblk>>>(x1, x2, 96, 192, wa3, 0, v);

    // attention weights
    attn_gemm_kernel<<<dim3(9,8), cblk>>>(q, k, attn);
    softmax_kernel<<<BATCH*CCH, 256>>>(attn);

    // attn @ v_unf  ==  per-batch 3x3 conv of v with weight A[b]
    conv3x3_kernel<<<cgrid, cblk>>>(v, v, 96, 96, attn, (long)CCH*CCH*9, y3);

    // batchnorm stats + fused epilogue
    bnstats_kernel<<<3*CCH, 256>>>(y1, y2, y3, meanv, istdv);
    int writeSecond = (out_size >= 2*N1OUT) ? 1 : 0;
    finalize_kernel<<<(N1OUT + 255)/256, 256>>>(x1, x2, y1, y2, y3, meanv, istdv, out, writeSecond);
}

// round 4
// speedup vs baseline: 1.5465x; 1.0766x over previous
#include <cuda_runtime.h>
#include <math.h>

#define BATCH 8
#define CCH 96
#define HH 96
#define WW 96
#define HW (HH*WW)                 // 9216
#define NPIX 7077888               // 8*96*96*96
#define N1OUT 14155776             // 8*192*96*96

// ---------------- scratch (static __device__, no allocation) ----------------
__device__ float g_y1[NPIX];
__device__ float g_y2[NPIX];
__device__ float g_q [NPIX];
__device__ float g_k [NPIX];
__device__ float g_v [NPIX];
__device__ float g_y3[NPIX];
__device__ float g_attn[BATCH*CCH*CCH*9];   // [b][ck][cq][p]
__device__ float g_mean[3*CCH];
__device__ float g_istd[3*CCH];

__device__ __forceinline__ unsigned f2tf32(float v) {
    unsigned u;
    asm("cvt.rna.tf32.f32 %0, %1;" : "=r"(u) : "f"(v));
    return u;
}

// ---------------- tensor-core 3x3 same-padding conv (tf32 mma.sync) --------
// conv = 9 shifted 1x1 GEMMs accumulated in fragments.
// input channels [0,csplit) from inA, [csplit,cin) from inB (virtual concat)
// weight OIHW: wgt[((co*cin)+ci)*9 + tap], optional per-batch stride.
// Block: 384 thr = 12 warps. Block tile: 96 co x 64 pix (8x8 spatial tile).
// Warp (wid): co group = (wid>>1)*16, pixel half ph = wid&1 (rows ph*4..+4).
// Per 8-ci chunk: W staged to smem [tap][ci][co] (TS=833, CS=104),
// patch staged [ci][row(12)][col] plane-stride 120; both tf32-rounded.
#define WTS 833      // wsm tap stride (words)
#define WCS 104      // wsm ci stride
#define PPS 120      // patch plane stride
#define PRS 12       // patch row stride

__global__ __launch_bounds__(384, 2)
void conv3x3_tc_kernel(const float* __restrict__ inA, const float* __restrict__ inB,
                       int csplit, int cin,
                       const float* __restrict__ wgt, long wbstride,
                       float* __restrict__ out)
{
    const int tid  = threadIdx.x;
    const int lane = tid & 31, wid = tid >> 5;
    const int g = lane >> 2, t = lane & 3;          // groupID, threadID-in-group
    const int cob = (wid >> 1) * 16;                // warp co base (0..80)
    const int ph  = wid & 1;                        // pixel-row half
    const int b   = blockIdx.z;
    const int byk = blockIdx.x / 12, bxk = blockIdx.x - 12*byk;
    const int by0 = byk*8, bx0 = bxk*8;

    __shared__ unsigned wsm[9*WTS];      // 9*833 words ≈ 29.3 KB
    __shared__ unsigned psm[8*PPS];      // 8*120 words = 3.75 KB

    const float* wb = wgt + (size_t)wbstride * b;

    float acc[4][4];
    #pragma unroll
    for (int q=0;q<4;q++)
        #pragma unroll
        for (int r=0;r<4;r++) acc[q][r] = 0.f;

    const int nchunk = cin >> 3;
    for (int ch = 0; ch < nchunk; ch++) {
        const int ci0 = ch << 3;
        if (ch) __syncthreads();

        // ---- stage W chunk: [co][ci(8)][tap(9)] gmem -> wsm[tap][ci][co] ----
        for (int e = tid; e < 96*72; e += 384) {
            int co = e / 72, r = e - co*72;
            int ci = r / 9,  tap = r - ci*9;
            float v = __ldg(wb + (size_t)co*cin*9 + (size_t)(ci0+ci)*9 + tap);
            wsm[tap*WTS + ci*WCS + co] = f2tf32(v);
        }
        // ---- stage input patch: 8 ci planes of 10x10 (halo 1) ----
        for (int e = tid; e < 800; e += 384) {
            int ci = e / 100, r2 = e - ci*100;
            int row = r2 / 10, col = r2 - row*10;
            int gh = by0 + row - 1, gw = bx0 + col - 1;
            int gci = ci0 + ci;
            float v = 0.f;
            if (gh >= 0 && gh < HH && gw >= 0 && gw < WW) {
                const float* src = (gci < csplit)
                    ? inA + ((size_t)b*csplit + gci)*HW
                    : inB + ((size_t)b*(cin-csplit) + (gci-csplit))*HW;
                v = __ldg(src + gh*WW + gw);
            }
            psm[ci*PPS + row*PRS + col] = f2tf32(v);
        }
        __syncthreads();

        // ---- 9 taps x 4 row-tiles of mma ----
        #pragma unroll
        for (int tap = 0; tap < 9; tap++) {
            const int i = tap / 3, j = tap - 3*(tap/3);
            const unsigned* wt = &wsm[tap*WTS];
            unsigned a0 = wt[ t   *WCS + cob + g    ];
            unsigned a1 = wt[ t   *WCS + cob + g + 8];
            unsigned a2 = wt[(t+4)*WCS + cob + g    ];
            unsigned a3 = wt[(t+4)*WCS + cob + g + 8];
            #pragma unroll
            for (int q = 0; q < 4; q++) {
                const int py = ph*4 + q;
                unsigned b0 = psm[ t   *PPS + (py+i)*PRS + g + j];
                unsigned b1 = psm[(t+4)*PPS + (py+i)*PRS + g + j];
                asm volatile(
                    "mma.sync.aligned.m16n8k8.row.col.f32.tf32.tf32.f32 "
                    "{%0,%1,%2,%3}, {%4,%5,%6,%7}, {%8,%9}, {%0,%1,%2,%3};"
                    : "+f"(acc[q][0]), "+f"(acc[q][1]),
                      "+f"(acc[q][2]), "+f"(acc[q][3])
                    : "r"(a0), "r"(a1), "r"(a2), "r"(a3), "r"(b0), "r"(b1));
            }
        }
    }

    // ---- writeback: c0/c1 -> (co, px, px+1), c2/c3 -> (co+8, px, px+1) ----
    #pragma unroll
    for (int q = 0; q < 4; q++) {
        int row = by0 + ph*4 + q;
        int co  = cob + g;
        int px  = bx0 + 2*t;
        float2 v01 = make_float2(acc[q][0], acc[q][1]);
        float2 v23 = make_float2(acc[q][2], acc[q][3]);
        *(float2*)&out[(((size_t)b*CCH + co    )*HH + row)*WW + px] = v01;
        *(float2*)&out[(((size_t)b*CCH + co + 8)*HH + row)*WW + px] = v23;
    }
}

// ---------------- attention GEMM (fp32) ----------------
__global__ __launch_bounds__(256)
void attn_gemm_kernel(const float* __restrict__ q, const float* __restrict__ k,
                      float* __restrict__ attn)
{
    const int p = blockIdx.x;        // 0..8
    const int b = blockIdx.y;        // 0..7
    const int i = p/3, j = p - 3*(p/3);
    const int tid = threadIdx.y*16 + threadIdx.x;

    __shared__ float Qs[16][96];
    __shared__ float Ks[16][96];

    float acc[6][6];
    #pragma unroll
    for (int r=0;r<6;r++)
        #pragma unroll
        for (int s=0;s<6;s++) acc[r][s]=0.f;

    for (int l0 = 0; l0 < 1024; l0 += 16) {
        #pragma unroll
        for (int it = 0; it < 6; it++) {
            int e = tid + it*256;                 // 16*96 = 1536 = 6*256
            int kk = e/96, c = e - kk*96;
            int l = l0 + kk;
            int gh = 3*(l>>5) + i, gw = 3*(l&31) + j;
            size_t off = ((size_t)(b*CCH + c)*HH + gh)*WW + gw;
            Qs[kk][c] = q[off];
            Ks[kk][c] = k[off];
        }
        __syncthreads();
        #pragma unroll
        for (int kk=0; kk<16; kk++) {
            float rq[6], rk[6];
            #pragma unroll
            for (int r=0;r<6;r++) {
                rq[r] = Qs[kk][threadIdx.y*6 + r];
                rk[r] = Ks[kk][threadIdx.x*6 + r];
            }
            #pragma unroll
            for (int r=0;r<6;r++)
                #pragma unroll
                for (int s=0;s<6;s++)
                    acc[r][s] = fmaf(rq[r], rk[s], acc[r][s]);
        }
        __syncthreads();
    }
    #pragma unroll
    for (int r=0;r<6;r++)
        #pragma unroll
        for (int s=0;s<6;s++) {
            int cq = threadIdx.y*6 + r, ck = threadIdx.x*6 + s;
            attn[((size_t)(b*CCH + ck)*CCH + cq)*9 + p] = acc[r][s];
        }
}

// ---------------- softmax over 864 per (b, ck) row ----------------
__global__ __launch_bounds__(256)
void softmax_kernel(float* __restrict__ attn)
{
    float* row = attn + (size_t)blockIdx.x * 864;
    const float scale = 0.034020690871988585f;   // 1/sqrt(864)
    const int tid = threadIdx.x;
    __shared__ float red[256];

    float v[4];
    float mx = -1e30f;
    #pragma unroll
    for (int it=0; it<4; it++) {
        int idx = tid + it*256;
        v[it] = (idx < 864) ? row[idx]*scale : -1e30f;
        mx = fmaxf(mx, v[it]);
    }
    red[tid] = mx; __syncthreads();
    for (int s=128; s>0; s>>=1) { if (tid<s) red[tid]=fmaxf(red[tid],red[tid+s]); __syncthreads(); }
    mx = red[0]; __syncthreads();

    float sum = 0.f;
    #pragma unroll
    for (int it=0; it<4; it++) {
        int idx = tid + it*256;
        v[it] = (idx < 864) ? expf(v[it]-mx) : 0.f;
        sum += v[it];
    }
    red[tid] = sum; __syncthreads();
    for (int s=128; s>0; s>>=1) { if (tid<s) red[tid]+=red[tid+s]; __syncthreads(); }
    float inv = 1.f/red[0];

    #pragma unroll
    for (int it=0; it<4; it++) {
        int idx = tid + it*256;
        if (idx < 864) row[idx] = v[it]*inv;
    }
}

// ---------------- batchnorm statistics (biased var) ----------------
__global__ __launch_bounds__(256)
void bnstats_kernel(const float* __restrict__ y1, const float* __restrict__ y2,
                    const float* __restrict__ y3,
                    float* __restrict__ meanv, float* __restrict__ istdv)
{
    const int t = blockIdx.x / CCH, c = blockIdx.x - t*CCH;
    const float* src = (t==0) ? y1 : (t==1) ? y2 : y3;
    float s = 0.f, sq = 0.f;
    for (int e = threadIdx.x; e < BATCH*HW; e += 256) {
        int b = e / HW, hw = e - b*HW;
        float vv = src[((size_t)b*CCH + c)*HW + hw];
        s += vv; sq = fmaf(vv, vv, sq);
    }
    __shared__ float sh1[256], sh2[256];
    sh1[threadIdx.x]=s; sh2[threadIdx.x]=sq;
    __syncthreads();
    for (int st=128; st>0; st>>=1) {
        if (threadIdx.x < st) { sh1[threadIdx.x]+=sh1[threadIdx.x+st]; sh2[threadIdx.x]+=sh2[threadIdx.x+st]; }
        __syncthreads();
    }
    if (threadIdx.x==0) {
        const float invN = 1.f / (float)(BATCH*HW);
        float m = sh1[0]*invN;
        float var = sh2[0]*invN - m*m;
        meanv[blockIdx.x] = m;
        istdv[blockIdx.x] = rsqrtf(var + 1e-5f);
    }
}

// ---------------- final fuse: out = (x+y, x) ----------------
__global__ __launch_bounds__(256)
void finalize_kernel(const float* __restrict__ x1, const float* __restrict__ x2,
                     const float* __restrict__ y1, const float* __restrict__ y2,
                     const float* __restrict__ y3,
                     const float* __restrict__ meanv, const float* __restrict__ istdv,
                     float* __restrict__ out, int writeSecond)
{
    int idx = blockIdx.x*256 + threadIdx.x;
    if (idx >= N1OUT) return;
    int hw = idx % HW;
    int c  = (idx / HW) % (2*CCH);
    int b  = idx / (HW*2*CCH);
    float xv, yv;
    if (c < CCH) {
        size_t off = ((size_t)b*CCH + c)*HW + hw;
        xv = x1[off];
        float a = (y1[off]-meanv[c])       * istdv[c];
        float g = (y2[off]-meanv[CCH+c])   * istdv[CCH+c];
        yv = a*g;
    } else {
        int cc = c - CCH;
        size_t off = ((size_t)b*CCH + cc)*HW + hw;
        xv = x2[off];
        yv = (y3[off]-meanv[2*CCH+cc]) * istdv[2*CCH+cc];
    }
    out[idx] = xv + yv;
    if (writeSecond) out[N1OUT + idx] = xv;
}

// ---------------- launch ----------------
extern "C" void kernel_launch(void* const* d_in, const int* in_sizes, int n_in,
                              void* d_out, int out_size)
{
    const float* x1  = (const float*)d_in[0];
    const float* x2  = (const float*)d_in[1];
    const float* w1  = (const float*)d_in[2];
    const float* w2  = (const float*)d_in[3];
    const float* wa1 = (const float*)d_in[4];
    const float* wa2 = (const float*)d_in[5];
    const float* wa3 = (const float*)d_in[6];
    float* out = (float*)d_out;

    float *y1,*y2,*q,*k,*v,*y3,*attn,*meanv,*istdv;
    cudaGetSymbolAddress((void**)&y1,   g_y1);
    cudaGetSymbolAddress((void**)&y2,   g_y2);
    cudaGetSymbolAddress((void**)&q,    g_q);
    cudaGetSymbolAddress((void**)&k,    g_k);
    cudaGetSymbolAddress((void**)&v,    g_v);
    cudaGetSymbolAddress((void**)&y3,   g_y3);
    cudaGetSymbolAddress((void**)&attn, g_attn);
    cudaGetSymbolAddress((void**)&meanv,g_mean);
    cudaGetSymbolAddress((void**)&istdv,g_istd);

    dim3 tcgrid(144, 1, 8);   // 12x12 pixel tiles of 8x8, 8 batches

    // fixed-weight convs (tensor cores, tf32)
    conv3x3_tc_kernel<<<tcgrid, 384>>>(x1, x1, 96,  96, w1,  0, y1);
    conv3x3_tc_kernel<<<tcgrid, 384>>>(x2, x2, 96,  96, w2,  0, y2);
    conv3x3_tc_kernel<<<tcgrid, 384>>>(x1, x2, 96, 192, wa1, 0, q);
    conv3x3_tc_kernel<<<tcgrid, 384>>>(x1, x2, 96, 192, wa2, 0, k);
    conv3x3_tc_kernel<<<tcgrid, 384>>>(x1, x2, 96, 192, wa3, 0, v);

    // attention weights
    dim3 cblk(16,16);
    attn_gemm_kernel<<<dim3(9,8), cblk>>>(q, k, attn);
    softmax_kernel<<<BATCH*CCH, 256>>>(attn);

    // attn @ v_unf  ==  per-batch 3x3 conv of v with weight A[b]
    conv3x3_tc_kernel<<<tcgrid, 384>>>(v, v, 96, 96, attn, (long)CCH*CCH*9, y3);

    // batchnorm stats + fused epilogue
    bnstats_kernel<<<3*CCH, 256>>>(y1, y2, y3, meanv, istdv);
    int writeSecond = (out_size >= 2*N1OUT) ? 1 : 0;
    finalize_kernel<<<(N1OUT + 255)/256, 256>>>(x1, x2, y1, y2, y3, meanv, istdv, out, writeSecond);
}

// round 5
// speedup vs baseline: 4.3371x; 2.8045x over previous
#include <cuda_runtime.h>
#include <math.h>

#define BATCH 8
#define CCH 96
#define HH 96
#define WW 96
#define HW (HH*WW)                 // 9216
#define NPIX 7077888               // 8*96*96*96
#define N1OUT 14155776             // 8*192*96*96

// weight-prep layout constants (words)
#define WCHUNK 7488                // 9 taps * 8 ci * 104 co
#define WTAP   832                 // 8 * 104
#define WCIS   104
// patch smem layout
#define PBUF   1600                // 8 ci * 10 rows * 20
#define PPS    200                 // plane stride
#define PRS    20                  // row stride
#define WBUF   WCHUNK

// ---------------- scratch (static __device__, no allocation) ----------------
__device__ float g_y1[NPIX];
__device__ float g_y2[NPIX];
__device__ float g_q [NPIX];
__device__ float g_k [NPIX];
__device__ float g_v [NPIX];
__device__ float g_y3[NPIX];
__device__ float g_attn[BATCH*CCH*CCH*9];   // [b][ck][cq][p]
__device__ float g_mean[3*CCH];
__device__ float g_istd[3*CCH];

// tf32 copies of conv inputs
__device__ __align__(16) unsigned g_x1t[NPIX];
__device__ __align__(16) unsigned g_x2t[NPIX];
__device__ __align__(16) unsigned g_vt [NPIX];
// pre-transformed tf32 weights in smem-ready layout
__device__ __align__(16) unsigned g_w1t [12*WCHUNK];
__device__ __align__(16) unsigned g_w2t [12*WCHUNK];
__device__ __align__(16) unsigned g_wa1t[24*WCHUNK];
__device__ __align__(16) unsigned g_wa2t[24*WCHUNK];
__device__ __align__(16) unsigned g_wa3t[24*WCHUNK];
__device__ __align__(16) unsigned g_wat [BATCH*12*WCHUNK];

__device__ __forceinline__ unsigned f2tf32(float v) {
    unsigned u;
    asm("cvt.rna.tf32.f32 %0, %1;" : "=r"(u) : "f"(v));
    return u;
}

// ---------------- input fp32 -> tf32 copy ----------------
__global__ __launch_bounds__(256)
void cvt_tf32_kernel(const float* __restrict__ src, unsigned* __restrict__ dst, int n)
{
    int i = blockIdx.x*256 + threadIdx.x;
    if (i < n) dst[i] = f2tf32(src[i]);
}

// ---------------- weight pre-transform ----------------
// src OIHW: wgt[((co*cin)+ci)*9+tap] (+ sbstride per batch)
// dst: [chunk][tap][ci8][co(104, pad0)] tf32 (+ dbstride per batch)
__global__ __launch_bounds__(256)
void wprep_kernel(const float* __restrict__ wgt, long sbstride, int cin,
                  unsigned* __restrict__ dst, long dbstride)
{
    const int b = blockIdx.z;
    const int nwords = (cin >> 3) * WCHUNK;
    int e = blockIdx.x*256 + threadIdx.x;
    if (e >= nwords) return;
    int chunk = e / WCHUNK, r = e - chunk*WCHUNK;
    int tap = r / WTAP;   r -= tap*WTAP;
    int ci8 = r / WCIS;
    int co  = r - ci8*WCIS;
    unsigned v = 0u;
    if (co < 96) {
        int ci = chunk*8 + ci8;
        v = f2tf32(wgt[sbstride*b + ((size_t)co*cin + ci)*9 + tap]);
    }
    dst[dbstride*b + (size_t)blockIdx.x*256 + threadIdx.x] = v;
}

// ---------------- tensor-core 3x3 conv, prepped tf32 operands ----------------
// block: 384 thr (12 warps) -> tile 96co x 128px (8 rows x 16 cols)
// warp: cog=wid>>2 (32 co), rp=wid&3 (rows 2rp,2rp+1); 2 m-tiles x 4 n-tiles
// double-buffered: weights via cp.async (contiguous), patch via LDG/STS (tf32 copy)
__global__ __launch_bounds__(384, 2)
void conv3x3_tc2_kernel(const unsigned* __restrict__ inAt, const unsigned* __restrict__ inBt,
                        int csplit, int cin,
                        const unsigned* __restrict__ wtf, long wbstride,
                        float* __restrict__ out)
{
    extern __shared__ unsigned dsm[];        // [2*WBUF weights][2*PBUF patch]
    const int tid  = threadIdx.x;
    const int lane = tid & 31, wid = tid >> 5;
    const int g = lane >> 2, t = lane & 3;
    const int cog = wid >> 2;                // 0..2
    const int rp  = wid & 3;                 // 0..3
    const int b   = blockIdx.z;
    const int byk = blockIdx.x / 6, bxk = blockIdx.x - 6*byk;
    const int by0 = byk*8, bx0 = bxk*16;

    const unsigned smem_b = (unsigned)__cvta_generic_to_shared(dsm);
    unsigned* psmem = dsm + 2*WBUF;

    // ---- hoisted patch geometry (1440 elems = 8ci x 10r x 18c) ----
    int pgoff[4], psoff[4], pci[4];
    bool lok[4], sok[4];
    #pragma unroll
    for (int it = 0; it < 4; it++) {
        int e = tid + it*384;
        int ci = e / 180, r2 = e - ci*180;
        int row = r2 / 18, col = r2 - row*18;
        int gh = by0 + row - 1, gw = bx0 + col - 1;
        bool inp = (e < 1440);
        bool ok = inp && gh >= 0 && gh < HH && gw >= 0 && gw < WW;
        lok[it] = ok; sok[it] = inp;
        pgoff[it] = ok ? gh*WW + gw : 0;
        psoff[it] = inp ? ci*PPS + row*PRS + col : 0;
        pci[it]   = ci;
    }

    const unsigned* wsrc0 = wtf + (size_t)wbstride*b;

    // ---- prologue: chunk 0 into buffer 0 ----
    #pragma unroll
    for (int k2 = 0; k2 < 5; k2++) {
        int idx = tid + k2*384;
        if (idx < 1872)
            asm volatile("cp.async.cg.shared.global [%0], [%1], 16;"
                         :: "r"(smem_b + idx*16), "l"(wsrc0 + idx*4) : "memory");
    }
    asm volatile("cp.async.commit_group;" ::: "memory");
    {
        unsigned pv[4];
        #pragma unroll
        for (int it = 0; it < 4; it++) {
            int gci = pci[it];
            const unsigned* src = (gci < csplit)
                ? inAt + ((size_t)b*csplit + gci)*HW
                : inBt + ((size_t)b*(cin-csplit) + (gci-csplit))*HW;
            pv[it] = lok[it] ? src[pgoff[it]] : 0u;
        }
        #pragma unroll
        for (int it = 0; it < 4; it++)
            if (sok[it]) psmem[psoff[it]] = pv[it];
    }
    asm volatile("cp.async.wait_group 0;" ::: "memory");
    __syncthreads();

    float acc[2][4][4];
    #pragma unroll
    for (int m=0;m<2;m++)
        #pragma unroll
        for (int nt=0;nt<4;nt++)
            #pragma unroll
            for (int r=0;r<4;r++) acc[m][nt][r] = 0.f;

    const int nchunk = cin >> 3;
    for (int ch = 0; ch < nchunk; ch++) {
        const int cur = ch & 1;
        const bool more = (ch + 1 < nchunk);

        // stage next chunk
        unsigned pv[4];
        if (more) {
            const unsigned* wsrc = wsrc0 + (size_t)(ch+1)*WCHUNK;
            const unsigned wdst = smem_b + (cur^1)*WBUF*4;
            #pragma unroll
            for (int k2 = 0; k2 < 5; k2++) {
                int idx = tid + k2*384;
                if (idx < 1872)
                    asm volatile("cp.async.cg.shared.global [%0], [%1], 16;"
                                 :: "r"(wdst + idx*16), "l"(wsrc + idx*4) : "memory");
            }
            asm volatile("cp.async.commit_group;" ::: "memory");
            const int ci0 = (ch+1) << 3;
            #pragma unroll
            for (int it = 0; it < 4; it++) {
                int gci = ci0 + pci[it];
                const unsigned* src = (gci < csplit)
                    ? inAt + ((size_t)b*csplit + gci)*HW
                    : inBt + ((size_t)b*(cin-csplit) + (gci-csplit))*HW;
                pv[it] = lok[it] ? src[pgoff[it]] : 0u;
            }
        }

        // ---- mma on current buffers ----
        const unsigned* wbf = dsm + cur*WBUF;
        const unsigned* pbf = psmem + cur*PBUF;
        #pragma unroll
        for (int tap = 0; tap < 9; tap++) {
            const int i = tap/3, j = tap - 3*(tap/3);
            const unsigned* wt = wbf + tap*WTAP;
            unsigned a[2][4];
            #pragma unroll
            for (int m = 0; m < 2; m++) {
                const int cb = cog*32 + m*16;
                a[m][0] = wt[ t   *WCIS + cb + g    ];
                a[m][1] = wt[ t   *WCIS + cb + g + 8];
                a[m][2] = wt[(t+4)*WCIS + cb + g    ];
                a[m][3] = wt[(t+4)*WCIS + cb + g + 8];
            }
            #pragma unroll
            for (int nt = 0; nt < 4; nt++) {
                const int py = 2*rp + (nt & 1);
                const int cb2 = (nt >> 1) * 8;
                unsigned b0 = pbf[ t   *PPS + (py+i)*PRS + cb2 + j + g];
                unsigned b1 = pbf[(t+4)*PPS + (py+i)*PRS + cb2 + j + g];
                #pragma unroll
                for (int m = 0; m < 2; m++) {
                    asm volatile(
                        "mma.sync.aligned.m16n8k8.row.col.f32.tf32.tf32.f32 "
                        "{%0,%1,%2,%3}, {%4,%5,%6,%7}, {%8,%9}, {%0,%1,%2,%3};"
                        : "+f"(acc[m][nt][0]), "+f"(acc[m][nt][1]),
                          "+f"(acc[m][nt][2]), "+f"(acc[m][nt][3])
                        : "r"(a[m][0]), "r"(a[m][1]), "r"(a[m][2]), "r"(a[m][3]),
                          "r"(b0), "r"(b1));
                }
            }
        }

        if (more) {
            unsigned* pd = psmem + (cur^1)*PBUF;
            #pragma unroll
            for (int it = 0; it < 4; it++)
                if (sok[it]) pd[psoff[it]] = pv[it];
            asm volatile("cp.async.wait_group 0;" ::: "memory");
        }
        __syncthreads();
    }

    // ---- writeback ----
    #pragma unroll
    for (int m = 0; m < 2; m++)
        #pragma unroll
        for (int nt = 0; nt < 4; nt++) {
            int co  = cog*32 + m*16 + g;
            int row = by0 + 2*rp + (nt & 1);
            int col = bx0 + (nt >> 1)*8 + 2*t;
            size_t base = (((size_t)b*CCH + co)*HH + row)*WW + col;
            *(float2*)&out[base]        = make_float2(acc[m][nt][0], acc[m][nt][1]);
            *(float2*)&out[base + 8*HW] = make_float2(acc[m][nt][2], acc[m][nt][3]);
        }
}

// ---------------- attention GEMM (fp32) ----------------
__global__ __launch_bounds__(256)
void attn_gemm_kernel(const float* __restrict__ q, const float* __restrict__ k,
                      float* __restrict__ attn)
{
    const int p = blockIdx.x;        // 0..8
    const int b = blockIdx.y;        // 0..7
    const int i = p/3, j = p - 3*(p/3);
    const int tid = threadIdx.y*16 + threadIdx.x;

    __shared__ float Qs[16][96];
    __shared__ float Ks[16][96];

    float acc[6][6];
    #pragma unroll
    for (int r=0;r<6;r++)
        #pragma unroll
        for (int s=0;s<6;s++) acc[r][s]=0.f;

    for (int l0 = 0; l0 < 1024; l0 += 16) {
        #pragma unroll
        for (int it = 0; it < 6; it++) {
            int e = tid + it*256;
            int kk = e/96, c = e - kk*96;
            int l = l0 + kk;
            int gh = 3*(l>>5) + i, gw = 3*(l&31) + j;
            size_t off = ((size_t)(b*CCH + c)*HH + gh)*WW + gw;
            Qs[kk][c] = q[off];
            Ks[kk][c] = k[off];
        }
        __syncthreads();
        #pragma unroll
        for (int kk=0; kk<16; kk++) {
            float rq[6], rk[6];
            #pragma unroll
            for (int r=0;r<6;r++) {
                rq[r] = Qs[kk][threadIdx.y*6 + r];
                rk[r] = Ks[kk][threadIdx.x*6 + r];
            }
            #pragma unroll
            for (int r=0;r<6;r++)
                #pragma unroll
                for (int s=0;s<6;s++)
                    acc[r][s] = fmaf(rq[r], rk[s], acc[r][s]);
        }
        __syncthreads();
    }
    #pragma unroll
    for (int r=0;r<6;r++)
        #pragma unroll
        for (int s=0;s<6;s++) {
            int cq = threadIdx.y*6 + r, ck = threadIdx.x*6 + s;
            attn[((size_t)(b*CCH + ck)*CCH + cq)*9 + p] = acc[r][s];
        }
}

// ---------------- softmax over 864 per (b, ck) row ----------------
__global__ __launch_bounds__(256)
void softmax_kernel(float* __restrict__ attn)
{
    float* row = attn + (size_t)blockIdx.x * 864;
    const float scale = 0.034020690871988585f;   // 1/sqrt(864)
    const int tid = threadIdx.x;
    __shared__ float red[256];

    float v[4];
    float mx = -1e30f;
    #pragma unroll
    for (int it=0; it<4; it++) {
        int idx = tid + it*256;
        v[it] = (idx < 864) ? row[idx]*scale : -1e30f;
        mx = fmaxf(mx, v[it]);
    }
    red[tid] = mx; __syncthreads();
    for (int s=128; s>0; s>>=1) { if (tid<s) red[tid]=fmaxf(red[tid],red[tid+s]); __syncthreads(); }
    mx = red[0]; __syncthreads();

    float sum = 0.f;
    #pragma unroll
    for (int it=0; it<4; it++) {
        int idx = tid + it*256;
        v[it] = (idx < 864) ? expf(v[it]-mx) : 0.f;
        sum += v[it];
    }
    red[tid] = sum; __syncthreads();
    for (int s=128; s>0; s>>=1) { if (tid<s) red[tid]+=red[tid+s]; __syncthreads(); }
    float inv = 1.f/red[0];

    #pragma unroll
    for (int it=0; it<4; it++) {
        int idx = tid + it*256;
        if (idx < 864) row[idx] = v[it]*inv;
    }
}

// ---------------- batchnorm statistics (biased var) ----------------
__global__ __launch_bounds__(256)
void bnstats_kernel(const float* __restrict__ y1, const float* __restrict__ y2,
                    const float* __restrict__ y3,
                    float* __restrict__ meanv, float* __restrict__ istdv)
{
    const int t = blockIdx.x / CCH, c = blockIdx.x - t*CCH;
    const float* src = (t==0) ? y1 : (t==1) ? y2 : y3;
    float s = 0.f, sq = 0.f;
    for (int e = threadIdx.x; e < BATCH*HW; e += 256) {
        int b = e / HW, hw = e - b*HW;
        float vv = src[((size_t)b*CCH + c)*HW + hw];
        s += vv; sq = fmaf(vv, vv, sq);
    }
    __shared__ float sh1[256], sh2[256];
    sh1[threadIdx.x]=s; sh2[threadIdx.x]=sq;
    __syncthreads();
    for (int st=128; st>0; st>>=1) {
        if (threadIdx.x < st) { sh1[threadIdx.x]+=sh1[threadIdx.x+st]; sh2[threadIdx.x]+=sh2[threadIdx.x+st]; }
        __syncthreads();
    }
    if (threadIdx.x==0) {
        const float invN = 1.f / (float)(BATCH*HW);
        float m = sh1[0]*invN;
        float var = sh2[0]*invN - m*m;
        meanv[blockIdx.x] = m;
        istdv[blockIdx.x] = rsqrtf(var + 1e-5f);
    }
}

// ---------------- final fuse: out = (x+y, x) ----------------
__global__ __launch_bounds__(256)
void finalize_kernel(const float* __restrict__ x1, const float* __restrict__ x2,
                     const float* __restrict__ y1, const float* __restrict__ y2,
                     const float* __restrict__ y3,
                     const float* __restrict__ meanv, const float* __restrict__ istdv,
                     float* __restrict__ out, int writeSecond)
{
    int idx = blockIdx.x*256 + threadIdx.x;
    if (idx >= N1OUT) return;
    int hw = idx % HW;
    int c  = (idx / HW) % (2*CCH);
    int b  = idx / (HW*2*CCH);
    float xv, yv;
    if (c < CCH) {
        size_t off = ((size_t)b*CCH + c)*HW + hw;
        xv = x1[off];
        float a = (y1[off]-meanv[c])       * istdv[c];
        float g = (y2[off]-meanv[CCH+c])   * istdv[CCH+c];
        yv = a*g;
    } else {
        int cc = c - CCH;
        size_t off = ((size_t)b*CCH + cc)*HW + hw;
        xv = x2[off];
        yv = (y3[off]-meanv[2*CCH+cc]) * istdv[2*CCH+cc];
    }
    out[idx] = xv + yv;
    if (writeSecond) out[N1OUT + idx] = xv;
}

// ---------------- launch ----------------
extern "C" void kernel_launch(void* const* d_in, const int* in_sizes, int n_in,
                              void* d_out, int out_size)
{
    const float* x1  = (const float*)d_in[0];
    const float* x2  = (const float*)d_in[1];
    const float* w1  = (const float*)d_in[2];
    const float* w2  = (const float*)d_in[3];
    const float* wa1 = (const float*)d_in[4];
    const float* wa2 = (const float*)d_in[5];
    const float* wa3 = (const float*)d_in[6];
    float* out = (float*)d_out;

    float *y1,*y2,*q,*k,*v,*y3,*attn,*meanv,*istdv;
    unsigned *x1t,*x2t,*vt,*w1t,*w2t,*wa1t,*wa2t,*wa3t,*wat;
    cudaGetSymbolAddress((void**)&y1,   g_y1);
    cudaGetSymbolAddress((void**)&y2,   g_y2);
    cudaGetSymbolAddress((void**)&q,    g_q);
    cudaGetSymbolAddress((void**)&k,    g_k);
    cudaGetSymbolAddress((void**)&v,    g_v);
    cudaGetSymbolAddress((void**)&y3,   g_y3);
    cudaGetSymbolAddress((void**)&attn, g_attn);
    cudaGetSymbolAddress((void**)&meanv,g_mean);
    cudaGetSymbolAddress((void**)&istdv,g_istd);
    cudaGetSymbolAddress((void**)&x1t,  g_x1t);
    cudaGetSymbolAddress((void**)&x2t,  g_x2t);
    cudaGetSymbolAddress((void**)&vt,   g_vt);
    cudaGetSymbolAddress((void**)&w1t,  g_w1t);
    cudaGetSymbolAddress((void**)&w2t,  g_w2t);
    cudaGetSymbolAddress((void**)&wa1t, g_wa1t);
    cudaGetSymbolAddress((void**)&wa2t, g_wa2t);
    cudaGetSymbolAddress((void**)&wa3t, g_wa3t);
    cudaGetSymbolAddress((void**)&wat,  g_wat);

    static int smem_set = 0;
    const int CONV_SMEM = (2*WBUF + 2*PBUF) * 4;   // 72704 B
    if (!smem_set) {
        cudaFuncSetAttribute(conv3x3_tc2_kernel,
                             cudaFuncAttributeMaxDynamicSharedMemorySize, CONV_SMEM);
        smem_set = 1;
    }

    // 1. inputs -> tf32
    cvt_tf32_kernel<<<(NPIX+255)/256, 256>>>(x1, x1t, NPIX);
    cvt_tf32_kernel<<<(NPIX+255)/256, 256>>>(x2, x2t, NPIX);

    // 2. weight pre-transform (fixed weights)
    wprep_kernel<<<dim3((12*WCHUNK+255)/256,1,1), 256>>>(w1,  0, 96,  w1t,  0);
    wprep_kernel<<<dim3((12*WCHUNK+255)/256,1,1), 256>>>(w2,  0, 96,  w2t,  0);
    wprep_kernel<<<dim3((24*WCHUNK+255)/256,1,1), 256>>>(wa1, 0, 192, wa1t, 0);
    wprep_kernel<<<dim3((24*WCHUNK+255)/256,1,1), 256>>>(wa2, 0, 192, wa2t, 0);
    wprep_kernel<<<dim3((24*WCHUNK+255)/256,1,1), 256>>>(wa3, 0, 192, wa3t, 0);

    dim3 tcgrid(72, 1, 8);   // 12 row-tiles x 6 col-tiles, 8 batches

    // 3. convs
    conv3x3_tc2_kernel<<<tcgrid, 384, CONV_SMEM>>>(x1t, x1t, 96,  96, w1t,  0, y1);
    conv3x3_tc2_kernel<<<tcgrid, 384, CONV_SMEM>>>(x2t, x2t, 96,  96, w2t,  0, y2);
    conv3x3_tc2_kernel<<<tcgrid, 384, CONV_SMEM>>>(x1t, x2t, 96, 192, wa1t, 0, q);
    conv3x3_tc2_kernel<<<tcgrid, 384, CONV_SMEM>>>(x1t, x2t, 96, 192, wa2t, 0, k);
    conv3x3_tc2_kernel<<<tcgrid, 384, CONV_SMEM>>>(x1t, x2t, 96, 192, wa3t, 0, v);

    // 4. attention weights
    dim3 cblk(16,16);
    attn_gemm_kernel<<<dim3(9,8), cblk>>>(q, k, attn);
    softmax_kernel<<<BATCH*CCH, 256>>>(attn);

    // 5. v -> tf32 ; attn weights -> prepped layout (per batch)
    cvt_tf32_kernel<<<(NPIX+255)/256, 256>>>(v, vt, NPIX);
    wprep_kernel<<<dim3((12*WCHUNK+255)/256,1,BATCH), 256>>>(attn, (long)CCH*CCH*9, 96, wat, 12L*WCHUNK);

    // 6. attn @ v_unf == per-batch 3x3 conv
    conv3x3_tc2_kernel<<<tcgrid, 384, CONV_SMEM>>>(vt, vt, 96, 96, wat, 12L*WCHUNK, y3);

    // 7. batchnorm stats + fused epilogue
    bnstats_kernel<<<3*CCH, 256>>>(y1, y2, y3, meanv, istdv);
    int writeSecond = (out_size >= 2*N1OUT) ? 1 : 0;
    finalize_kernel<<<(N1OUT + 255)/256, 256>>>(x1, x2, y1, y2, y3, meanv, istdv, out, writeSecond);
}